// round 5
// baseline (speedup 1.0000x reference)
#include <cuda_runtime.h>
#include <math.h>

// Problem shape (fixed for this dataset): B=32768, T=512, C=128 channels=3.
#define MAX_B 32768
#define T_LEN 512

// Scratch (static device globals — no allocation).
__device__ float g_row_loss[MAX_B];
__device__ int   g_scores[MAX_B];
__device__ int   g_is64;

// ---------------------------------------------------------------------------
// Kernel 0: detect labels dtype. If int64 (little-endian), all odd 32-bit
// words among the first B words are high halves of values in [0,128) => 0.
// ---------------------------------------------------------------------------
__global__ void detect_labels_kernel(const int* __restrict__ lw, int B) {
    __shared__ int sm[1024];
    int a = 0;
    for (int i = 2 * threadIdx.x + 1; i < B; i += 2048) a |= lw[i];
    sm[threadIdx.x] = a;
    __syncthreads();
    for (int st = 512; st; st >>= 1) {
        if (threadIdx.x < st) sm[threadIdx.x] |= sm[threadIdx.x + st];
        __syncthreads();
    }
    if (threadIdx.x == 0) g_is64 = (sm[0] == 0) ? 1 : 0;
}

// ---------------------------------------------------------------------------
// Kernel 1: physics score per window. One CTA (128 threads) per window.
// Window = 512 timesteps x 3 channels = 1536 floats = 6 KiB in SMEM.
// ---------------------------------------------------------------------------
__global__ __launch_bounds__(128) void physics_kernel(const float* __restrict__ imu) {
    __shared__ float s[T_LEN * 3];
    __shared__ float redf[6][4];
    __shared__ int   redi[2][4];

    const int b   = blockIdx.x;
    const int tid = threadIdx.x;
    const unsigned FULL = 0xffffffffu;

    // Coalesced load: 1536 floats = 384 float4, 128 threads x 3.
    const float4* src = reinterpret_cast<const float4*>(imu + (size_t)b * (T_LEN * 3));
    float4* dst = reinterpret_cast<float4*>(s);
#pragma unroll
    for (int i = 0; i < 3; i++) dst[tid + i * 128] = src[tid + i * 128];
    __syncthreads();

    // ---- Pass 1: per-channel sum and max(|w|) ----
    float sum0 = 0.f, sum1 = 0.f, sum2 = 0.f;
    float mx0 = 0.f, mx1 = 0.f, mx2 = 0.f;
#pragma unroll
    for (int k = 0; k < 4; k++) {
        int t = tid + k * 128;
        float w0 = s[3 * t], w1 = s[3 * t + 1], w2 = s[3 * t + 2];
        sum0 += w0; sum1 += w1; sum2 += w2;
        mx0 = fmaxf(mx0, fabsf(w0));
        mx1 = fmaxf(mx1, fabsf(w1));
        mx2 = fmaxf(mx2, fabsf(w2));
    }
#pragma unroll
    for (int o = 16; o; o >>= 1) {
        sum0 += __shfl_xor_sync(FULL, sum0, o);
        sum1 += __shfl_xor_sync(FULL, sum1, o);
        sum2 += __shfl_xor_sync(FULL, sum2, o);
        mx0 = fmaxf(mx0, __shfl_xor_sync(FULL, mx0, o));
        mx1 = fmaxf(mx1, __shfl_xor_sync(FULL, mx1, o));
        mx2 = fmaxf(mx2, __shfl_xor_sync(FULL, mx2, o));
    }
    const int warp = tid >> 5;
    if ((tid & 31) == 0) {
        redf[0][warp] = sum0; redf[1][warp] = sum1; redf[2][warp] = sum2;
        redf[3][warp] = mx0;  redf[4][warp] = mx1;  redf[5][warp] = mx2;
    }
    __syncthreads();
    const float m0 = (redf[0][0] + redf[0][1] + redf[0][2] + redf[0][3]) * (1.0f / 512.0f);
    const float m1 = (redf[1][0] + redf[1][1] + redf[1][2] + redf[1][3]) * (1.0f / 512.0f);
    const float m2 = (redf[2][0] + redf[2][1] + redf[2][2] + redf[2][3]) * (1.0f / 512.0f);
    const float M0 = fmaxf(fmaxf(redf[3][0], redf[3][1]), fmaxf(redf[3][2], redf[3][3]));
    const float M1 = fmaxf(fmaxf(redf[4][0], redf[4][1]), fmaxf(redf[4][2], redf[4][3]));
    const float M2 = fmaxf(fmaxf(redf[5][0], redf[5][1]), fmaxf(redf[5][2], redf[5][3]));
    __syncthreads();  // all reads of redf done before it is reused below

    // ---- Pass 2: tv, at_max counts, zero-crossings (ch0), jerk outliers ----
    float tv = 0.f;
    int c0 = 0, c1 = 0, c2 = 0, zc = 0, jc = 0;
#pragma unroll
    for (int k = 0; k < 4; k++) {
        int t = tid + k * 128;
        float w0 = s[3 * t], w1 = s[3 * t + 1], w2 = s[3 * t + 2];
        float d0 = w0 - m0, d1 = w1 - m1, d2 = w2 - m2;
        tv += d0 * d0 + d1 * d1 + d2 * d2;
        c0 += (fabsf(fabsf(w0) - M0) < 0.01f);
        c1 += (fabsf(fabsf(w1) - M1) < 0.01f);
        c2 += (fabsf(fabsf(w2) - M2) < 0.01f);
        if (t < T_LEN - 1) {
            float e0 = s[3 * t + 3] - m0;
            zc += (d0 * e0 < 0.0f);
        }
        if (t < T_LEN - 4) {
            // vel[t] = (w[t+2]-w[t])/(2dt); jerk[t] = (vel[t+2]-vel[t])/(2dt); 1/(2dt)=25
#pragma unroll
            for (int c = 0; c < 3; c++) {
                float a  = s[3 * t + c];
                float bm = s[3 * (t + 2) + c];
                float cm = s[3 * (t + 4) + c];
                float vA = (bm - a) * 25.0f;
                float vB = (cm - bm) * 25.0f;
                jc += (fabsf((vB - vA) * 25.0f) > 5000.0f);
            }
        }
    }
    // Pack counters: c0..c2 <= 512 (10 bits each), zc <= 511, jc <= 1524.
    int pa = c0 | (c1 << 10) | (c2 << 20);
    int pb = zc | (jc << 16);
#pragma unroll
    for (int o = 16; o; o >>= 1) {
        tv += __shfl_xor_sync(FULL, tv, o);
        pa += __shfl_xor_sync(FULL, pa, o);
        pb += __shfl_xor_sync(FULL, pb, o);
    }
    if ((tid & 31) == 0) {
        redf[0][warp] = tv;
        redi[0][warp] = pa;
        redi[1][warp] = pb;
    }
    __syncthreads();

    if (tid == 0) {
        float tvT = (redf[0][0] + redf[0][1] + redf[0][2] + redf[0][3]) * (1.0f / 512.0f);
        int paT = redi[0][0] + redi[0][1] + redi[0][2] + redi[0][3];
        int pbT = redi[1][0] + redi[1][1] + redi[1][2] + redi[1][3];
        int cc0 = paT & 1023, cc1 = (paT >> 10) & 1023, cc2 = (paT >> 20) & 1023;
        int zcc = pbT & 0xffff, jcc = pbT >> 16;

        bool reject = tvT < 0.005f;
        reject |= (M0 >= 0.5f) && ((float)cc0 * (1.0f / 512.0f) > 0.2f);
        reject |= (M1 >= 0.5f) && ((float)cc1 * (1.0f / 512.0f) > 0.2f);
        reject |= (M2 >= 0.5f) && ((float)cc2 * (1.0f / 512.0f) > 0.2f);
        // js[p95_idx]>5000 with p95_idx=int(1524*0.95)=1447  <=>  count(>5000) >= 77
        reject |= (jcc >= 77);

        float s1 = tvT > 10.0f ? 90.0f : (tvT > 2.0f ? 80.0f : (tvT > 0.5f ? 70.0f : 58.0f));
        float zcr = (float)zcc * (1.0f / 512.0f);
        float s2 = zcr > 0.15f ? 85.0f : (zcr > 0.07f ? 70.0f : 55.0f);
        int score = (int)floorf((s1 + s2) * 0.5f);
        g_scores[b] = reject ? 0 : score;
    }
}

// ---------------------------------------------------------------------------
// Kernel 2: per-row NLL. One warp per row (128 logits = 32 x float4).
// ---------------------------------------------------------------------------
__global__ __launch_bounds__(256) void task_loss_kernel(const float* __restrict__ preds,
                                                        const int* __restrict__ labels_w,
                                                        int B) {
    const unsigned FULL = 0xffffffffu;
    int row  = blockIdx.x * 8 + (threadIdx.x >> 5);
    int lane = threadIdx.x & 31;
    if (row >= B) return;

    const float4* p4 = reinterpret_cast<const float4*>(preds + (size_t)row * 128);
    float4 v = p4[lane];
    float mx = fmaxf(fmaxf(v.x, v.y), fmaxf(v.z, v.w));
#pragma unroll
    for (int o = 16; o; o >>= 1) mx = fmaxf(mx, __shfl_xor_sync(FULL, mx, o));
    float sum = expf(v.x - mx) + expf(v.y - mx) + expf(v.z - mx) + expf(v.w - mx);
#pragma unroll
    for (int o = 16; o; o >>= 1) sum += __shfl_xor_sync(FULL, sum, o);

    if (lane == 0) {
        int lbl = g_is64 ? labels_w[2 * (size_t)row] : labels_w[row];
        float pl = preds[(size_t)row * 128 + lbl];
        g_row_loss[row] = logf(sum) + mx - pl;  // = -(pl - logsumexp)
    }
}

// ---------------------------------------------------------------------------
// Kernel 3: deterministic fixed-order final reduction + combine.
// ---------------------------------------------------------------------------
__global__ __launch_bounds__(1024) void finalize_kernel(float* __restrict__ out, int B) {
    __shared__ float sf[1024];
    __shared__ int   si[1024];
    float ls = 0.f;
    int   sc = 0;
    for (int i = threadIdx.x; i < B; i += 1024) {
        ls += g_row_loss[i];
        sc += g_scores[i];
    }
    sf[threadIdx.x] = ls;
    si[threadIdx.x] = sc;
    __syncthreads();
    for (int st = 512; st; st >>= 1) {
        if (threadIdx.x < st) {
            sf[threadIdx.x] += sf[threadIdx.x + st];
            si[threadIdx.x] += si[threadIdx.x + st];
        }
        __syncthreads();
    }
    if (threadIdx.x == 0) {
        float task_loss = sf[0] / (float)B;
        // mean(1 - s/100) = 1 - sum(s)/(100*B), exact integer sum
        float penalty = 1.0f - (float)si[0] / ((float)B * 100.0f);
        out[0] = task_loss + 0.3f * penalty;
    }
}

// ---------------------------------------------------------------------------
extern "C" void kernel_launch(void* const* d_in, const int* in_sizes, int n_in,
                              void* d_out, int out_size) {
    const float* preds    = (const float*)d_in[0];
    const int*   labels_w = (const int*)d_in[1];   // int32 view; dtype detected on device
    const float* imu      = (const float*)d_in[2];
    const int B = in_sizes[1];  // labels element count

    detect_labels_kernel<<<1, 1024>>>(labels_w, B);
    physics_kernel<<<B, 128>>>(imu);
    task_loss_kernel<<<(B + 7) / 8, 256>>>(preds, labels_w, B);
    finalize_kernel<<<1, 1024>>>((float*)d_out, B);
}

// round 6
// speedup vs baseline: 1.0669x; 1.0669x over previous
#include <cuda_runtime.h>
#include <math.h>

// Problem shape: B=32768, T=512, channels=3, C=128 logits.
#define T_LEN 512
#define LOSS_SCALE 4194304.0f   // 2^22 fixed point for deterministic loss sum

// Integer accumulators => deterministic regardless of CTA order.
__device__ unsigned long long g_loss_acc = 0ULL;
__device__ int                g_score_acc = 0;
__device__ unsigned int       g_done = 0u;

__global__ __launch_bounds__(128) void fused_kernel(
    const float* __restrict__ imu,
    const float* __restrict__ preds,
    const int*   __restrict__ labels_w,   // raw 32-bit view of labels buffer
    float*       __restrict__ out,
    int B)
{
    const int tid  = threadIdx.x;
    const int warp = tid >> 5;
    const int lane = tid & 31;
    const unsigned FULL = 0xffffffffu;

    // Shared: physics window (padded +48 floats so tid=127's halo read stays
    // in-bounds; pad contents are never used) + reduction scratch + task losses.
    __shared__ float s[T_LEN * 3 + 48];
    __shared__ float redf[6][4];
    __shared__ int   redi[2][4];
    __shared__ float lsh[4];

    if (blockIdx.x < (unsigned)B) {
        // ================= PHYSICS: one CTA per window =================
        const int b = blockIdx.x;

        // Coalesced load: 1536 floats = 384 float4.
        const float4* src = reinterpret_cast<const float4*>(imu + (size_t)b * (T_LEN * 3));
        float4* dst = reinterpret_cast<float4*>(s);
#pragma unroll
        for (int i = 0; i < 3; i++) dst[tid + i * 128] = src[tid + i * 128];
        __syncthreads();

        // Each thread: own timesteps t0..t0+3 (12 floats) + halo t0+4..t0+7.
        // 6x LDS.128, conflict-free (bank stride 12 mod 32 covers all banks/phase).
        __align__(16) float f[24];
        const float4* sv = reinterpret_cast<const float4*>(s + 12 * tid);
#pragma unroll
        for (int j = 0; j < 6; j++) *reinterpret_cast<float4*>(f + 4 * j) = sv[j];

        // ---- Pass 1: per-channel sum and max(|w|) over own 4 timesteps ----
        float sum0 = 0.f, sum1 = 0.f, sum2 = 0.f;
        float mx0 = 0.f, mx1 = 0.f, mx2 = 0.f;
#pragma unroll
        for (int i = 0; i < 4; i++) {
            float w0 = f[3 * i], w1 = f[3 * i + 1], w2 = f[3 * i + 2];
            sum0 += w0; sum1 += w1; sum2 += w2;
            mx0 = fmaxf(mx0, fabsf(w0));
            mx1 = fmaxf(mx1, fabsf(w1));
            mx2 = fmaxf(mx2, fabsf(w2));
        }
#pragma unroll
        for (int o = 16; o; o >>= 1) {
            sum0 += __shfl_xor_sync(FULL, sum0, o);
            sum1 += __shfl_xor_sync(FULL, sum1, o);
            sum2 += __shfl_xor_sync(FULL, sum2, o);
            mx0 = fmaxf(mx0, __shfl_xor_sync(FULL, mx0, o));
            mx1 = fmaxf(mx1, __shfl_xor_sync(FULL, mx1, o));
            mx2 = fmaxf(mx2, __shfl_xor_sync(FULL, mx2, o));
        }
        if (lane == 0) {
            redf[0][warp] = sum0; redf[1][warp] = sum1; redf[2][warp] = sum2;
            redf[3][warp] = mx0;  redf[4][warp] = mx1;  redf[5][warp] = mx2;
        }
        __syncthreads();
        const float m0 = (redf[0][0] + redf[0][1] + redf[0][2] + redf[0][3]) * (1.0f / 512.0f);
        const float m1 = (redf[1][0] + redf[1][1] + redf[1][2] + redf[1][3]) * (1.0f / 512.0f);
        const float m2 = (redf[2][0] + redf[2][1] + redf[2][2] + redf[2][3]) * (1.0f / 512.0f);
        const float M0 = fmaxf(fmaxf(redf[3][0], redf[3][1]), fmaxf(redf[3][2], redf[3][3]));
        const float M1 = fmaxf(fmaxf(redf[4][0], redf[4][1]), fmaxf(redf[4][2], redf[4][3]));
        const float M2 = fmaxf(fmaxf(redf[5][0], redf[5][1]), fmaxf(redf[5][2], redf[5][3]));
        __syncthreads();   // redf reads done before reuse below

        // ---- Pass 2: entirely from registers ----
        float tv = 0.f;
        int c0 = 0, c1 = 0, c2 = 0, zc = 0, jc = 0;
        const bool notLast = (tid != 127);
#pragma unroll
        for (int i = 0; i < 4; i++) {
            float w0 = f[3 * i], w1 = f[3 * i + 1], w2 = f[3 * i + 2];
            float d0 = w0 - m0, d1 = w1 - m1, d2 = w2 - m2;
            tv += d0 * d0 + d1 * d1 + d2 * d2;
            c0 += (fabsf(fabsf(w0) - M0) < 0.01f);
            c1 += (fabsf(fabsf(w1) - M1) < 0.01f);
            c2 += (fabsf(fabsf(w2) - M2) < 0.01f);
            // zero crossings (channel 0), pairs t..t+1 for t < 511
            if (notLast || i < 3) {
                float e0 = f[3 * (i + 1)] - m0;   // i+1<=4 -> f[12] = halo
                zc += (d0 * e0 < 0.0f);
            }
            // jerk outliers, t < 508 (tid=127 has no valid t)
            if (notLast) {
#pragma unroll
                for (int c = 0; c < 3; c++) {
                    float a  = f[3 * i + c];
                    float bm = f[3 * (i + 2) + c];
                    float cm = f[3 * (i + 4) + c];   // i+4<=7 -> halo
                    float vA = (bm - a) * 25.0f;
                    float vB = (cm - bm) * 25.0f;
                    jc += (fabsf((vB - vA) * 25.0f) > 5000.0f);
                }
            }
        }
        // Pack counters: c* <= 512 (10 bits), zc <= 511, jc <= 1524.
        int pa = c0 | (c1 << 10) | (c2 << 20);
        int pb = zc | (jc << 16);
#pragma unroll
        for (int o = 16; o; o >>= 1) {
            tv += __shfl_xor_sync(FULL, tv, o);
            pa += __shfl_xor_sync(FULL, pa, o);
            pb += __shfl_xor_sync(FULL, pb, o);
        }
        if (lane == 0) {
            redf[0][warp] = tv;
            redi[0][warp] = pa;
            redi[1][warp] = pb;
        }
        __syncthreads();

        if (tid == 0) {
            float tvT = (redf[0][0] + redf[0][1] + redf[0][2] + redf[0][3]) * (1.0f / 512.0f);
            int paT = redi[0][0] + redi[0][1] + redi[0][2] + redi[0][3];
            int pbT = redi[1][0] + redi[1][1] + redi[1][2] + redi[1][3];
            int cc0 = paT & 1023, cc1 = (paT >> 10) & 1023, cc2 = (paT >> 20) & 1023;
            int zcc = pbT & 0xffff, jcc = pbT >> 16;

            bool reject = tvT < 0.005f;
            reject |= (M0 >= 0.5f) && ((float)cc0 * (1.0f / 512.0f) > 0.2f);
            reject |= (M1 >= 0.5f) && ((float)cc1 * (1.0f / 512.0f) > 0.2f);
            reject |= (M2 >= 0.5f) && ((float)cc2 * (1.0f / 512.0f) > 0.2f);
            reject |= (jcc >= 77);   // js[1447] > 5000  <=>  count(>5000) >= 77

            float s1 = tvT > 10.0f ? 90.0f : (tvT > 2.0f ? 80.0f : (tvT > 0.5f ? 70.0f : 58.0f));
            float zcr = (float)zcc * (1.0f / 512.0f);
            float s2 = zcr > 0.15f ? 85.0f : (zcr > 0.07f ? 70.0f : 55.0f);
            int score = (int)floorf((s1 + s2) * 0.5f);
            if (!reject) atomicAdd(&g_score_acc, score);
        }
        __syncthreads();
    } else {
        // ================= TASK LOSS: 4 rows per CTA (1 warp/row) =========
        const int idx = blockIdx.x - B;
        const int row = idx * 4 + warp;

        // Labels dtype detection from first 128 words (L2-hit after CTA 0):
        // int64 little-endian => all odd words (high halves of values <128) == 0.
        int a = labels_w[2 * lane + 1] | labels_w[2 * (lane + 32) + 1];
#pragma unroll
        for (int o = 16; o; o >>= 1) a |= __shfl_xor_sync(FULL, a, o);
        const int is64 = (a == 0);

        if (row < B) {
            const float4* p4 = reinterpret_cast<const float4*>(preds + (size_t)row * 128);
            float4 v = p4[lane];
            float mx = fmaxf(fmaxf(v.x, v.y), fmaxf(v.z, v.w));
#pragma unroll
            for (int o = 16; o; o >>= 1) mx = fmaxf(mx, __shfl_xor_sync(FULL, mx, o));
            float sum = expf(v.x - mx) + expf(v.y - mx) + expf(v.z - mx) + expf(v.w - mx);
#pragma unroll
            for (int o = 16; o; o >>= 1) sum += __shfl_xor_sync(FULL, sum, o);
            if (lane == 0) {
                int lbl = is64 ? labels_w[2 * (size_t)row] : labels_w[row];
                float pl = preds[(size_t)row * 128 + lbl];
                lsh[warp] = logf(sum) + mx - pl;   // -(pl - logsumexp) >= 0
            }
        } else if (lane == 0) {
            lsh[warp] = 0.f;
        }
        __syncthreads();
        if (tid == 0) {
            unsigned long long acc = 0ULL;
#pragma unroll
            for (int j = 0; j < 4; j++)
                acc += (unsigned long long)llrintf(lsh[j] * LOSS_SCALE);
            atomicAdd(&g_loss_acc, acc);
        }
        __syncthreads();
    }

    // ============ Last-CTA finalize (deterministic: integer sums) ============
    if (tid == 0) {
        __threadfence();
        unsigned int done = atomicAdd(&g_done, 1u);
        if (done == gridDim.x - 1) {
            unsigned long long L = atomicAdd(&g_loss_acc, 0ULL);
            int S = atomicAdd(&g_score_acc, 0);
            double task = (double)L / ((double)LOSS_SCALE * (double)B);
            double pen  = 1.0 - (double)S / (100.0 * (double)B);
            out[0] = (float)(task + 0.3 * pen);
            // Reset state so the captured graph replays identically.
            atomicExch(&g_loss_acc, 0ULL);
            atomicExch(&g_score_acc, 0);
            __threadfence();
            atomicExch(&g_done, 0u);
        }
    }
}

// ---------------------------------------------------------------------------
extern "C" void kernel_launch(void* const* d_in, const int* in_sizes, int n_in,
                              void* d_out, int out_size) {
    const float* preds    = (const float*)d_in[0];
    const int*   labels_w = (const int*)d_in[1];
    const float* imu      = (const float*)d_in[2];
    const int B = in_sizes[1];            // 32768

    const int grid = B + (B + 3) / 4;     // physics CTAs + task CTAs
    fused_kernel<<<grid, 128>>>(imu, preds, labels_w, (float*)d_out, B);
}